// round 4
// baseline (speedup 1.0000x reference)
#include <cuda_runtime.h>
#include <math.h>

// Problem constants
#define NENT   4096
#define ANON   4
#define NTOT   (NENT + ANON)   // 4100
#define DIM    128
#define BATCH  8
#define EPS    1e-10f

#define TPB    512
#define WPB    (TPB / 32)          // 16 warps/block
#define NBLK   64
#define NWARP  (NBLK * WPB)        // 1024 warps -> 4 rows each (+1 for warps 0..3)
#define STRIDE NWARP               // 1024

// Scratch (no cudaMalloc allowed)
__device__ float        g_x1[NTOT];   // exp(-e_all.w1)
__device__ float        g_x2[NTOT];   // exp(-e_all.w2)
__device__ float        g_rw1[BATCH];
__device__ float        g_cw1[BATCH];
__device__ unsigned int g_counter = 0;

__device__ __forceinline__ float warp_bfly_sum(float s) {
    #pragma unroll
    for (int o = 16; o > 0; o >>= 1)
        s += __shfl_xor_sync(0xffffffffu, s, o);
    return s;
}

// ---------------------------------------------------------------------------
// Single fused kernel, last-block finalize.
//   m[b] = 1 / min_j (1 + x1[j]*t1[b]) * (1 + x2[j]*t2[b])
//   t1[b] = exp(-(rw1[b]+bias)) * min_x2   (min_x2 == exp(-ci_max))
//   t2[b] = exp(-(cw1[b]+bias))
//   loss = mean_b -log(1 - m[b] + EPS)
// ---------------------------------------------------------------------------
__global__ void __launch_bounds__(TPB)
falcon_fused_kernel(const int*   __restrict__ x,
                    const float* __restrict__ anon_e,
                    const float* __restrict__ c_table,
                    const float* __restrict__ r_table,
                    const float* __restrict__ e_table,
                    const float* __restrict__ fc_w,
                    const float* __restrict__ fc_b,
                    float*       __restrict__ out)
{
    __shared__ unsigned int s_islast;

    int tid  = threadIdx.x;
    int warp = tid >> 5;
    int lane = tid & 31;
    int wg   = blockIdx.x * WPB + warp;      // global warp id, 0..1023

    // ---------------- Phase 1: entity dot products + exp ----------------
    float4 w1 = reinterpret_cast<const float4*>(fc_w)[lane];        // w[0:128]
    float4 w2 = reinterpret_cast<const float4*>(fc_w + DIM)[lane];  // w[128:256]

    // 4 independent row loads (front-batched, MLP=4). All rows < NENT.
    float4 v0 = reinterpret_cast<const float4*>(e_table + (size_t)(wg         ) * DIM)[lane];
    float4 v1 = reinterpret_cast<const float4*>(e_table + (size_t)(wg + STRIDE) * DIM)[lane];
    float4 v2 = reinterpret_cast<const float4*>(e_table + (size_t)(wg + 2*STRIDE) * DIM)[lane];
    float4 v3 = reinterpret_cast<const float4*>(e_table + (size_t)(wg + 3*STRIDE) * DIM)[lane];

    float s10 = v0.x*w1.x + v0.y*w1.y + v0.z*w1.z + v0.w*w1.w;
    float s20 = v0.x*w2.x + v0.y*w2.y + v0.z*w2.z + v0.w*w2.w;
    float s11 = v1.x*w1.x + v1.y*w1.y + v1.z*w1.z + v1.w*w1.w;
    float s21 = v1.x*w2.x + v1.y*w2.y + v1.z*w2.z + v1.w*w2.w;
    float s12 = v2.x*w1.x + v2.y*w1.y + v2.z*w1.z + v2.w*w1.w;
    float s22 = v2.x*w2.x + v2.y*w2.y + v2.z*w2.z + v2.w*w2.w;
    float s13 = v3.x*w1.x + v3.y*w1.y + v3.z*w1.z + v3.w*w1.w;
    float s23 = v3.x*w2.x + v3.y*w2.y + v3.z*w2.z + v3.w*w2.w;

    s10 = warp_bfly_sum(s10);  s20 = warp_bfly_sum(s20);
    s11 = warp_bfly_sum(s11);  s21 = warp_bfly_sum(s21);
    s12 = warp_bfly_sum(s12);  s22 = warp_bfly_sum(s22);
    s13 = warp_bfly_sum(s13);  s23 = warp_bfly_sum(s23);

    // distribute the 8 exps over 8 lanes (each lane holds all totals)
    if      (lane == 0) g_x1[wg           ] = expf(-s10);
    else if (lane == 1) g_x2[wg           ] = expf(-s20);
    else if (lane == 2) g_x1[wg +   STRIDE] = expf(-s11);
    else if (lane == 3) g_x2[wg +   STRIDE] = expf(-s21);
    else if (lane == 4) g_x1[wg + 2*STRIDE] = expf(-s12);
    else if (lane == 5) g_x2[wg + 2*STRIDE] = expf(-s22);
    else if (lane == 6) g_x1[wg + 3*STRIDE] = expf(-s13);
    else if (lane == 7) g_x2[wg + 3*STRIDE] = expf(-s23);

    // 4 anon rows: warps 0..3 take a 5th row
    if (wg < ANON) {
        float4 va = reinterpret_cast<const float4*>(anon_e + (size_t)wg * DIM)[lane];
        float sa1 = va.x*w1.x + va.y*w1.y + va.z*w1.z + va.w*w1.w;
        float sa2 = va.x*w2.x + va.y*w2.y + va.z*w2.z + va.w*w2.w;
        sa1 = warp_bfly_sum(sa1);
        sa2 = warp_bfly_sum(sa2);
        if      (lane == 0) g_x1[NENT + wg] = expf(-sa1);
        else if (lane == 1) g_x2[NENT + wg] = expf(-sa2);
    }

    // block 0 also computes the gathered r/c dot products (overlapped)
    if (blockIdx.x == 0) {
        int b = warp & 7;
        const float* row = (warp < 8)
            ? (r_table + (size_t)x[2 * b]     * DIM)
            : (c_table + (size_t)x[2 * b + 1] * DIM);
        float4 v  = reinterpret_cast<const float4*>(row)[lane];
        float s = v.x*w1.x + v.y*w1.y + v.z*w1.z + v.w*w1.w;
        s = warp_bfly_sum(s);
        if (lane == 0) {
            if (warp < 8) g_rw1[b] = s;
            else          g_cw1[b] = s;
        }
    }

    // ---------------- election ----------------
    __syncthreads();
    if (tid == 0) {
        __threadfence();                       // release all global writes
        unsigned int prev = atomicAdd(&g_counter, 1u);
        s_islast = (prev == NBLK - 1) ? 1u : 0u;
    }
    __syncthreads();
    if (s_islast == 0u) return;

    // ---------------- Phase 2: last block finalizes ----------------
    __threadfence();                           // acquire

    __shared__ float s_red[WPB];
    __shared__ float s_t1[BATCH];
    __shared__ float s_t2[BATCH];
    __shared__ float s_dmin[BATCH][WPB];

    // min over g_x2  (== exp(-ci_max)); L2-hot 16KB pass
    float m = 3.402823466e+38f;
    for (int j = tid; j < NTOT; j += TPB)
        m = fminf(m, g_x2[j]);
    #pragma unroll
    for (int o = 16; o > 0; o >>= 1)
        m = fminf(m, __shfl_xor_sync(0xffffffffu, m, o));
    if (lane == 0) s_red[warp] = m;
    __syncthreads();

    const float bias = fc_b[0];
    if (tid < BATCH) {
        float minx2 = s_red[0];
        #pragma unroll
        for (int w = 1; w < WPB; w++) minx2 = fminf(minx2, s_red[w]);
        s_t1[tid] = expf(-(g_rw1[tid] + bias)) * minx2;
        s_t2[tid] = expf(-(g_cw1[tid] + bias));
    }
    __syncthreads();

    float t1[BATCH], t2[BATCH];
    #pragma unroll
    for (int b = 0; b < BATCH; b++) { t1[b] = s_t1[b]; t2[b] = s_t2[b]; }

    float dmin[BATCH];
    #pragma unroll
    for (int b = 0; b < BATCH; b++) dmin[b] = 3.402823466e+38f;

    for (int j = tid; j < NTOT; j += TPB) {
        float x1 = g_x1[j];
        float x2 = g_x2[j];
        #pragma unroll
        for (int b = 0; b < BATCH; b++) {
            float d1 = fmaf(x1, t1[b], 1.0f);
            float d2 = fmaf(x2, t2[b], 1.0f);
            dmin[b] = fminf(dmin[b], d1 * d2);
        }
    }

    #pragma unroll
    for (int b = 0; b < BATCH; b++) {
        float v = dmin[b];
        #pragma unroll
        for (int o = 16; o > 0; o >>= 1)
            v = fminf(v, __shfl_xor_sync(0xffffffffu, v, o));
        if (lane == 0) s_dmin[b][warp] = v;
    }
    __syncthreads();

    if (tid == 0) {
        float loss = 0.0f;
        #pragma unroll
        for (int b = 0; b < BATCH; b++) {
            float dm = s_dmin[b][0];
            #pragma unroll
            for (int w = 1; w < WPB; w++) dm = fminf(dm, s_dmin[b][w]);
            float mb = 1.0f / dm;              // max_j sigmoid product
            loss += -logf(1.0f - mb + EPS);
        }
        out[0] = loss * (1.0f / (float)BATCH);
        g_counter = 0u;                        // reset for next graph replay
    }
}

// ---------------------------------------------------------------------------
// Input order (metadata): x, anon_e_emb, c_table, r_table, e_table, fc_w, fc_b
// ---------------------------------------------------------------------------
extern "C" void kernel_launch(void* const* d_in, const int* in_sizes, int n_in,
                              void* d_out, int out_size)
{
    const int*   x        = (const int*)  d_in[0];
    const float* anon_e   = (const float*)d_in[1];
    const float* c_table  = (const float*)d_in[2];
    const float* r_table  = (const float*)d_in[3];
    const float* e_table  = (const float*)d_in[4];
    const float* fc_w     = (const float*)d_in[5];
    const float* fc_b     = (const float*)d_in[6];
    float*       out      = (float*)d_out;

    falcon_fused_kernel<<<NBLK, TPB>>>(x, anon_e, c_table, r_table,
                                       e_table, fc_w, fc_b, out);
}

// round 5
// speedup vs baseline: 1.2134x; 1.2134x over previous
#include <cuda_runtime.h>
#include <math.h>

// Problem constants
#define NENT   4096
#define ANON   4
#define NTOT   (NENT + ANON)   // 4100
#define DIM    128
#define BATCH  8
#define EPS    1e-10f

#define TPB    512
#define WPB    (TPB / 32)                       // 16 warps/block
#define NWORK  (NTOT + 2 * BATCH)               // 4116 warps of work
#define NBLK_A ((NWORK + WPB - 1) / WPB)        // 258 blocks

#define FLT_MAX_F    3.402823466e+38f
#define FLT_MAX_BITS 0x7F7FFFFFu

// Scratch (no cudaMalloc allowed)
__device__ float        g_x1[NTOT];                  // exp(-e_all.w1)
__device__ float        g_x2[NTOT];                  // exp(-e_all.w2)
__device__ float        g_rw1[BATCH];
__device__ float        g_cw1[BATCH];
__device__ unsigned int g_x2min_bits = FLT_MAX_BITS; // reset by kernel B

__device__ __forceinline__ float warp_bfly_sum(float s) {
    #pragma unroll
    for (int o = 16; o > 0; o >>= 1)
        s += __shfl_xor_sync(0xffffffffu, s, o);
    return s;
}

// ---------------------------------------------------------------------------
// Kernel A: warp-per-row. Rows 0..4099 = entity dots -> exp(-dot) to globals.
// Warps 4100..4115 = gathered r/c dot products. Per-block min(x2) -> atomicMin.
// ---------------------------------------------------------------------------
__global__ void __launch_bounds__(TPB)
falcon_ew_kernel(const int*   __restrict__ x,
                 const float* __restrict__ anon_e,
                 const float* __restrict__ c_table,
                 const float* __restrict__ r_table,
                 const float* __restrict__ e_table,
                 const float* __restrict__ fc_w)
{
    __shared__ float s_wmin[WPB];

    int tid  = threadIdx.x;
    int warp = tid >> 5;
    int lane = tid & 31;
    int gw   = blockIdx.x * WPB + warp;

    float4 w1 = reinterpret_cast<const float4*>(fc_w)[lane];        // w[0:128]

    float wx2 = FLT_MAX_F;

    if (gw < NTOT) {
        // entity row
        const float* row = (gw < NENT)
            ? (e_table + (size_t)gw * DIM)
            : (anon_e + (size_t)(gw - NENT) * DIM);
        float4 w2 = reinterpret_cast<const float4*>(fc_w + DIM)[lane];
        float4 v  = reinterpret_cast<const float4*>(row)[lane];

        float s1 = v.x*w1.x + v.y*w1.y + v.z*w1.z + v.w*w1.w;
        float s2 = v.x*w2.x + v.y*w2.y + v.z*w2.z + v.w*w2.w;
        s1 = warp_bfly_sum(s1);
        s2 = warp_bfly_sum(s2);

        if (lane == 0) {
            g_x1[gw] = expf(-s1);
        } else if (lane == 1) {
            float x2 = expf(-s2);
            g_x2[gw] = x2;
            wx2 = x2;
        }
    } else if (gw < NWORK) {
        // gathered dot products: g in [0,8) -> rw1, [8,16) -> cw1
        int g = gw - NTOT;
        int b = g & 7;
        const float* row = (g < 8)
            ? (r_table + (size_t)x[2 * b]     * DIM)
            : (c_table + (size_t)x[2 * b + 1] * DIM);
        float4 v = reinterpret_cast<const float4*>(row)[lane];
        float s = v.x*w1.x + v.y*w1.y + v.z*w1.z + v.w*w1.w;
        s = warp_bfly_sum(s);
        if (lane == 0) {
            if (g < 8) g_rw1[b] = s;
            else       g_cw1[b] = s;
        }
    }

    // block-level min of x2 (positive floats -> bit ordering valid)
    if (lane == 1) s_wmin[warp] = wx2;
    __syncthreads();
    if (tid == 0) {
        float bm = s_wmin[0];
        #pragma unroll
        for (int w = 1; w < WPB; w++) bm = fminf(bm, s_wmin[w]);
        if (bm < FLT_MAX_F)
            atomicMin(&g_x2min_bits, __float_as_uint(bm));
    }
}

// ---------------------------------------------------------------------------
// Kernel B: single block.
//   m[b] = 1 / min_j (1 + x1[j]*t1[b]) * (1 + x2[j]*t2[b])
//   t1[b] = exp(-(rw1[b]+bias)) * min_x2     (min_x2 == exp(-ci_max))
//   t2[b] = exp(-(cw1[b]+bias))
//   loss  = mean_b -log(1 - m[b] + EPS)
// ---------------------------------------------------------------------------
__global__ void __launch_bounds__(TPB)
falcon_finalize_kernel(const float* __restrict__ fc_b,
                       float*       __restrict__ out)
{
    __shared__ float s_t1[BATCH];
    __shared__ float s_t2[BATCH];
    __shared__ float s_dmin[BATCH][WPB];

    int tid  = threadIdx.x;
    int warp = tid >> 5;
    int lane = tid & 31;

    if (tid < BATCH) {
        float bias  = fc_b[0];
        float minx2 = __uint_as_float(g_x2min_bits);
        s_t1[tid] = expf(-(g_rw1[tid] + bias)) * minx2;
        s_t2[tid] = expf(-(g_cw1[tid] + bias));
    }
    __syncthreads();

    float t1[BATCH], t2[BATCH];
    #pragma unroll
    for (int b = 0; b < BATCH; b++) { t1[b] = s_t1[b]; t2[b] = s_t2[b]; }

    float dmin[BATCH];
    #pragma unroll
    for (int b = 0; b < BATCH; b++) dmin[b] = FLT_MAX_F;

    for (int j = tid; j < NTOT; j += TPB) {
        float x1 = g_x1[j];
        float x2 = g_x2[j];
        #pragma unroll
        for (int b = 0; b < BATCH; b++) {
            float d1 = fmaf(x1, t1[b], 1.0f);
            float d2 = fmaf(x2, t2[b], 1.0f);
            dmin[b] = fminf(dmin[b], d1 * d2);
        }
    }

    #pragma unroll
    for (int b = 0; b < BATCH; b++) {
        float v = dmin[b];
        #pragma unroll
        for (int o = 16; o > 0; o >>= 1)
            v = fminf(v, __shfl_xor_sync(0xffffffffu, v, o));
        if (lane == 0) s_dmin[b][warp] = v;
    }
    __syncthreads();

    if (tid == 0) {
        float loss = 0.0f;
        #pragma unroll
        for (int b = 0; b < BATCH; b++) {
            float dm = s_dmin[b][0];
            #pragma unroll
            for (int w = 1; w < WPB; w++) dm = fminf(dm, s_dmin[b][w]);
            float mb = 1.0f / dm;              // max_j sigmoid product
            loss += -logf(1.0f - mb + EPS);
        }
        out[0] = loss * (1.0f / (float)BATCH);
        g_x2min_bits = FLT_MAX_BITS;           // reset for next graph replay
    }
}

// ---------------------------------------------------------------------------
// Input order (metadata): x, anon_e_emb, c_table, r_table, e_table, fc_w, fc_b
// ---------------------------------------------------------------------------
extern "C" void kernel_launch(void* const* d_in, const int* in_sizes, int n_in,
                              void* d_out, int out_size)
{
    const int*   x        = (const int*)  d_in[0];
    const float* anon_e   = (const float*)d_in[1];
    const float* c_table  = (const float*)d_in[2];
    const float* r_table  = (const float*)d_in[3];
    const float* e_table  = (const float*)d_in[4];
    const float* fc_w     = (const float*)d_in[5];
    const float* fc_b     = (const float*)d_in[6];
    float*       out      = (float*)d_out;

    falcon_ew_kernel<<<NBLK_A, TPB>>>(x, anon_e, c_table, r_table,
                                      e_table, fc_w);
    falcon_finalize_kernel<<<1, TPB>>>(fc_b, out);
}

// round 6
// speedup vs baseline: 1.3296x; 1.0958x over previous
#include <cuda_runtime.h>
#include <math.h>

// Problem constants
#define NENT   4096
#define ANON   4
#define NTOT   (NENT + ANON)   // 4100
#define DIM    128
#define BATCH  8
#define EPS    1e-10f

#define TPB    512
#define WPB    (TPB / 32)                       // 16 warps/block
#define NWORK  (NTOT + 2 * BATCH)               // 4116 warps of work
#define NBLK_A ((NWORK + WPB - 1) / WPB)        // 258 blocks

#define FLT_MAX_F    3.402823466e+38f
#define FLT_MAX_BITS 0x7F7FFFFFu

// Scratch (no cudaMalloc allowed)
__device__ float        g_x1[NTOT];                  // exp(-e_all.w1)
__device__ float        g_x2[NTOT];                  // exp(-e_all.w2)
__device__ float        g_rw1[BATCH];
__device__ float        g_cw1[BATCH];
__device__ unsigned int g_x2min_bits = FLT_MAX_BITS; // reset by kernel B

__device__ __forceinline__ float warp_bfly_sum(float s) {
    #pragma unroll
    for (int o = 16; o > 0; o >>= 1)
        s += __shfl_xor_sync(0xffffffffu, s, o);
    return s;
}

// ---------------------------------------------------------------------------
// Kernel A: warp-per-row. Rows 0..4099 = entity dots -> exp(-dot) to globals.
// Warps 4100..4115 = gathered r/c dot products. Per-block min(x2) -> atomicMin.
// ---------------------------------------------------------------------------
__global__ void __launch_bounds__(TPB)
falcon_ew_kernel(const int*   __restrict__ x,
                 const float* __restrict__ anon_e,
                 const float* __restrict__ c_table,
                 const float* __restrict__ r_table,
                 const float* __restrict__ e_table,
                 const float* __restrict__ fc_w)
{
    __shared__ float s_wmin[WPB];

    int tid  = threadIdx.x;
    int warp = tid >> 5;
    int lane = tid & 31;
    int gw   = blockIdx.x * WPB + warp;

    float4 w1 = reinterpret_cast<const float4*>(fc_w)[lane];        // w[0:128]

    float wx2 = FLT_MAX_F;

    if (gw < NTOT) {
        // entity row
        const float* row = (gw < NENT)
            ? (e_table + (size_t)gw * DIM)
            : (anon_e + (size_t)(gw - NENT) * DIM);
        float4 w2 = reinterpret_cast<const float4*>(fc_w + DIM)[lane];
        float4 v  = reinterpret_cast<const float4*>(row)[lane];

        float s1 = v.x*w1.x + v.y*w1.y + v.z*w1.z + v.w*w1.w;
        float s2 = v.x*w2.x + v.y*w2.y + v.z*w2.z + v.w*w2.w;
        s1 = warp_bfly_sum(s1);
        s2 = warp_bfly_sum(s2);

        if (lane == 0) {
            g_x1[gw] = expf(-s1);
        } else if (lane == 1) {
            float x2 = expf(-s2);
            g_x2[gw] = x2;
            wx2 = x2;
        }
    } else if (gw < NWORK) {
        // gathered dot products: g in [0,8) -> rw1, [8,16) -> cw1
        int g = gw - NTOT;
        int b = g & 7;
        const float* row = (g < 8)
            ? (r_table + (size_t)x[2 * b]     * DIM)
            : (c_table + (size_t)x[2 * b + 1] * DIM);
        float4 v = reinterpret_cast<const float4*>(row)[lane];
        float s = v.x*w1.x + v.y*w1.y + v.z*w1.z + v.w*w1.w;
        s = warp_bfly_sum(s);
        if (lane == 0) {
            if (g < 8) g_rw1[b] = s;
            else       g_cw1[b] = s;
        }
    }

    // block-level min of x2 (positive floats -> bit ordering valid)
    if (lane == 1) s_wmin[warp] = wx2;
    __syncthreads();
    if (tid == 0) {
        float bm = s_wmin[0];
        #pragma unroll
        for (int w = 1; w < WPB; w++) bm = fminf(bm, s_wmin[w]);
        if (bm < FLT_MAX_F)
            atomicMin(&g_x2min_bits, __float_as_uint(bm));
    }
}

// ---------------------------------------------------------------------------
// Kernel B: single block.
//   m[b] = 1 / min_j (1 + x1[j]*t1[b]) * (1 + x2[j]*t2[b])
//   t1[b] = exp(-(rw1[b]+bias)) * min_x2     (min_x2 == exp(-ci_max))
//   t2[b] = exp(-(cw1[b]+bias))
//   loss  = mean_b -log(1 - m[b] + EPS)
// ---------------------------------------------------------------------------
__global__ void __launch_bounds__(TPB)
falcon_finalize_kernel(const float* __restrict__ fc_b,
                       float*       __restrict__ out)
{
    __shared__ float s_t1[BATCH];
    __shared__ float s_t2[BATCH];
    __shared__ float s_dmin[BATCH][WPB];

    int tid  = threadIdx.x;
    int warp = tid >> 5;
    int lane = tid & 31;

    if (tid < BATCH) {
        float bias  = fc_b[0];
        float minx2 = __uint_as_float(g_x2min_bits);
        s_t1[tid] = expf(-(g_rw1[tid] + bias)) * minx2;
        s_t2[tid] = expf(-(g_cw1[tid] + bias));
    }
    __syncthreads();

    float t1[BATCH], t2[BATCH];
    #pragma unroll
    for (int b = 0; b < BATCH; b++) { t1[b] = s_t1[b]; t2[b] = s_t2[b]; }

    float dmin[BATCH];
    #pragma unroll
    for (int b = 0; b < BATCH; b++) dmin[b] = FLT_MAX_F;

    for (int j = tid; j < NTOT; j += TPB) {
        float x1 = g_x1[j];
        float x2 = g_x2[j];
        #pragma unroll
        for (int b = 0; b < BATCH; b++) {
            float d1 = fmaf(x1, t1[b], 1.0f);
            float d2 = fmaf(x2, t2[b], 1.0f);
            dmin[b] = fminf(dmin[b], d1 * d2);
        }
    }

    #pragma unroll
    for (int b = 0; b < BATCH; b++) {
        float v = dmin[b];
        #pragma unroll
        for (int o = 16; o > 0; o >>= 1)
            v = fminf(v, __shfl_xor_sync(0xffffffffu, v, o));
        if (lane == 0) s_dmin[b][warp] = v;
    }
    __syncthreads();

    if (tid == 0) {
        float loss = 0.0f;
        #pragma unroll
        for (int b = 0; b < BATCH; b++) {
            float dm = s_dmin[b][0];
            #pragma unroll
            for (int w = 1; w < WPB; w++) dm = fminf(dm, s_dmin[b][w]);
            float mb = 1.0f / dm;              // max_j sigmoid product
            loss += -logf(1.0f - mb + EPS);
        }
        out[0] = loss * (1.0f / (float)BATCH);
        g_x2min_bits = FLT_MAX_BITS;           // reset for next graph replay
    }
}

// ---------------------------------------------------------------------------
// Input order (metadata): x, anon_e_emb, c_table, r_table, e_table, fc_w, fc_b
// ---------------------------------------------------------------------------
extern "C" void kernel_launch(void* const* d_in, const int* in_sizes, int n_in,
                              void* d_out, int out_size)
{
    const int*   x        = (const int*)  d_in[0];
    const float* anon_e   = (const float*)d_in[1];
    const float* c_table  = (const float*)d_in[2];
    const float* r_table  = (const float*)d_in[3];
    const float* e_table  = (const float*)d_in[4];
    const float* fc_w     = (const float*)d_in[5];
    const float* fc_b     = (const float*)d_in[6];
    float*       out      = (float*)d_out;

    falcon_ew_kernel<<<NBLK_A, TPB>>>(x, anon_e, c_table, r_table,
                                      e_table, fc_w);
    falcon_finalize_kernel<<<1, TPB>>>(fc_b, out);
}